// round 17
// baseline (speedup 1.0000x reference)
#include <cuda_runtime.h>
#include <cstdint>

// CausalDAG fused, warp-specialized persistent kernel for GB300 (sm_103a). R15.
//   m = A^T x (producer warps, exact fp32 fma2, A from __constant__)
//   h = elu(W1_c @ m + b1); out = W2_c @ h + b2   (bf16 m16n8k16, 3-mma comp)
//
// Base = R8 (177us best). Changes:
//  * ALL of W1 (hi+lo fragments, 128 KB) staged in smem once per CTA: phase-2
//    weight loads become 29-cyc LDS instead of serialized 234-cyc L2 windows
//    (R11 moving only the hi half was neutral because q2/q3 kept the window).
//  * Single m tile buffer (fits beside W1): phase-3 still overlaps next mix.
//  * A in __constant__ (uniform-path loads, removes producer broadcast-LDS).

#define Cc 16
#define Dd 64
#define Gg 32
#define NTH 512
#define ROWU2 36            // uint2 (hi,lo) pairs per row incl. pad
#define CTU2 (16 * ROWU2)   // uint2 per concept block = 576
#define TILEU2 (Cc * CTU2)  // 9216 uint2 = 73728 B

#define W1S_BYTES 131072    // 8192 uint4
#define MBUF_OFF  W1S_BYTES
#define SMEM_TOTAL (W1S_BYTES + TILEU2 * 8)   // 204800 B

typedef unsigned long long ull;

__constant__ float4 cA4[64];    // A[16][16] as float4 rows

// Prepacked bf16 hi/lo weight fragments (same layout as R8).
__device__ uint4 W1pk[Cc * 4 * 4 * 32];
__device__ uint4 W2pk[Cc * 8 * 2 * 32];

__device__ __forceinline__ ull fma2(ull a, ull b, ull c) {
    ull d;
    asm("fma.rn.f32x2 %0, %1, %2, %3;" : "=l"(d) : "l"(a), "l"(b), "l"(c));
    return d;
}
__device__ __forceinline__ ull dup2(float a) {
    ull d;
    asm("mov.b64 %0, {%1, %1};" : "=l"(d) : "f"(a));
    return d;
}
__device__ __forceinline__ uint32_t pack_bf16_2(float lo, float hi) {
    uint32_t r;
    asm("cvt.rn.bf16x2.f32 %0, %1, %2;" : "=r"(r) : "f"(hi), "f"(lo));
    return r;
}
__device__ __forceinline__ void split_pair(float f0, float f1,
                                           uint32_t& hi, uint32_t& lo) {
    hi = pack_bf16_2(f0, f1);
    float f0h = __uint_as_float(hi << 16);
    float f1h = __uint_as_float(hi & 0xffff0000u);
    lo = pack_bf16_2(f0 - f0h, f1 - f1h);
}
__device__ __forceinline__ void mma_bf16(float c[4],
                                         uint32_t a0, uint32_t a1, uint32_t a2, uint32_t a3,
                                         uint32_t b0, uint32_t b1) {
    asm volatile(
        "mma.sync.aligned.m16n8k16.row.col.f32.bf16.bf16.f32 "
        "{%0,%1,%2,%3}, {%4,%5,%6,%7}, {%8,%9}, {%0,%1,%2,%3};"
        : "+f"(c[0]), "+f"(c[1]), "+f"(c[2]), "+f"(c[3])
        : "r"(a0), "r"(a1), "r"(a2), "r"(a3), "r"(b0), "r"(b1));
}
__device__ __forceinline__ float elu1(float v) {
    return v > 0.0f ? v : (__expf(v) - 1.0f);
}

// ---------------- Prep: pack weights into bf16 hi/lo fragment order ----------
__global__ void __launch_bounds__(256)
pack_weights(const float* __restrict__ W1, const float* __restrict__ W2)
{
    const int t = blockIdx.x * 256 + threadIdx.x;   // 0..16383
    const int half = t >> 13;
    const int u = t & 8191;
    const int lane = u & 31;
    const int grp  = lane >> 2;
    const int tig  = lane & 3;

    uint4 v;
    if (half == 0) {
        const int q  = (u >> 5) & 3;
        const int kt = (u >> 7) & 3;
        const int c  = u >> 9;
        const bool lo_sel = q >= 2;
        const int ntA = (q & 1) * 2;
        #pragma unroll
        for (int j = 0; j < 2; j++) {
            const int nt = ntA + j;
            const int g  = nt * 8 + grp;
            const float* wr = W1 + ((size_t)c * Gg + g) * Dd + kt * 16 + 2 * tig;
            uint32_t h0, l0, h1, l1;
            split_pair(wr[0], wr[1], h0, l0);
            split_pair(wr[8], wr[9], h1, l1);
            if (j == 0) { v.x = lo_sel ? l0 : h0; v.y = lo_sel ? l1 : h1; }
            else        { v.z = lo_sel ? l0 : h0; v.w = lo_sel ? l1 : h1; }
        }
        W1pk[u] = v;
    } else {
        const int hl = (u >> 5) & 1;
        const int nt = (u >> 6) & 7;
        const int c  = u >> 9;
        const int d  = nt * 8 + grp;
        #pragma unroll
        for (int kt = 0; kt < 2; kt++) {
            const float* wr = W2 + ((size_t)c * Dd + d) * Gg + kt * 16 + 2 * tig;
            uint32_t h0, l0, h1, l1;
            split_pair(wr[0], wr[1], h0, l0);
            split_pair(wr[8], wr[9], h1, l1);
            uint32_t e0 = hl ? l0 : h0, e1 = hl ? l1 : h1;
            if (kt == 0) { v.x = e0; v.y = e1; }
            else         { v.z = e0; v.w = e1; }
        }
        W2pk[u] = v;
    }
}

extern __shared__ char smem_raw[];
// [0, 131072): W1 fragment cache (full hi+lo); [131072, 204800): m tile buffer

__global__ void __launch_bounds__(NTH, 1)
causal_dag_kernel(const float* __restrict__ x,
                  const float* __restrict__ b1, const float* __restrict__ b2,
                  float* __restrict__ out, int nPairs)
{
    uint4* W1s  = (uint4*)smem_raw;
    uint2* mbuf = (uint2*)(smem_raw + MBUF_OFF);
    const int tid = threadIdx.x;

    // Stage full W1 fragment set into smem (coalesced, once per CTA).
    #pragma unroll
    for (int r = 0; r < 16; r++)
        W1s[r * NTH + tid] = W1pk[r * NTH + tid];
    __syncthreads();

    if (tid < 256) {
        // ======================= PRODUCER (warps 0-7) ========================
        const int bl = tid >> 4;               // 0..15 local batch row
        const int dq = tid & 15;               // float4 chunk of D=64
        bool first = true;
        for (int p = blockIdx.x; p < nPairs; p += gridDim.x) {
            #pragma unroll
            for (int sub = 0; sub < 2; sub++) {
                if (!first)
                    asm volatile("bar.sync 2, 512;" ::: "memory"); // EMPTY
                first = false;
                const int tile = 2 * p + sub;
                const float4* xb =
                    (const float4*)(x + (size_t)(tile * 16 + bl) * (Cc * Dd)) + dq;

                ull mrx[Cc], mrz[Cc];
                #pragma unroll
                for (int i = 0; i < Cc; i++) { mrx[i] = 0ull; mrz[i] = 0ull; }
                #pragma unroll
                for (int j = 0; j < Cc; j++) {
                    const float4 f = __ldcs(xb + j * 16);   // streaming
                    ull xlo, xhi;
                    asm("mov.b64 %0, {%2, %3}; mov.b64 %1, {%4, %5};"
                        : "=l"(xlo), "=l"(xhi)
                        : "f"(f.x), "f"(f.y), "f"(f.z), "f"(f.w));
                    #pragma unroll
                    for (int i4 = 0; i4 < 4; i4++) {
                        const float4 av = cA4[j * 4 + i4];  // uniform constant
                        float a4[4] = {av.x, av.y, av.z, av.w};
                        #pragma unroll
                        for (int ii = 0; ii < 4; ii++) {
                            ull a2 = dup2(a4[ii]);
                            mrx[i4 * 4 + ii] = fma2(a2, xlo, mrx[i4 * 4 + ii]);
                            mrz[i4 * 4 + ii] = fma2(a2, xhi, mrz[i4 * 4 + ii]);
                        }
                    }
                }
                #pragma unroll
                for (int i = 0; i < Cc; i++) {
                    float f0, f1, g0, g1;
                    asm("mov.b64 {%0, %1}, %2;" : "=f"(f0), "=f"(f1) : "l"(mrx[i]));
                    asm("mov.b64 {%0, %1}, %2;" : "=f"(g0), "=f"(g1) : "l"(mrz[i]));
                    uint4 v;
                    split_pair(f0, f1, v.x, v.y);
                    split_pair(g0, g1, v.z, v.w);
                    *(uint4*)&mbuf[(i * 16 + bl) * ROWU2 + 2 * dq] = v;
                }
                asm volatile("bar.arrive 1, 512;" ::: "memory");   // FULL
            }
        }
    } else {
        // ======================= CONSUMER (warps 8-15) =======================
        const int cw   = (tid >> 5) - 8;       // 0..7, owns concepts 2cw,2cw+1
        const int lane = tid & 31;
        const int grp  = lane >> 2;
        const int tig  = lane & 3;

        for (int p = blockIdx.x; p < nPairs; p += gridDim.x) {
            uint32_t hfh[2][2][8], hfl[2][2][8];   // [s][t][kt'*4+r]

            #pragma unroll
            for (int t = 0; t < 2; t++) {
                asm volatile("bar.sync 1, 512;" ::: "memory");     // FULL
                #pragma unroll
                for (int s = 0; s < 2; s++) {
                    const int c = 2 * cw + s;
                    const uint2* mc = mbuf + c * CTU2;

                    float acc[4][4];
                    #pragma unroll
                    for (int nt = 0; nt < 4; nt++)
                        #pragma unroll
                        for (int q = 0; q < 4; q++) acc[nt][q] = 0.0f;

                    #pragma unroll
                    for (int kt = 0; kt < 4; kt++) {
                        const int pi = kt * 8 + tig;
                        const uint2 a0 = mc[grp * ROWU2 + pi];
                        const uint2 a1 = mc[(grp + 8) * ROWU2 + pi];
                        const uint2 a2 = mc[grp * ROWU2 + pi + 4];
                        const uint2 a3 = mc[(grp + 8) * ROWU2 + pi + 4];
                        const int wb = ((c * 4 + kt) * 4) * 32 + lane;
                        const uint4 q0 = W1s[wb];          // 29-cyc LDS now
                        const uint4 q1 = W1s[wb + 32];
                        const uint4 q2 = W1s[wb + 64];
                        const uint4 q3 = W1s[wb + 96];
                        // nt0
                        mma_bf16(acc[0], a0.x, a1.x, a2.x, a3.x, q0.x, q0.y);
                        mma_bf16(acc[0], a0.y, a1.y, a2.y, a3.y, q0.x, q0.y);
                        mma_bf16(acc[0], a0.x, a1.x, a2.x, a3.x, q2.x, q2.y);
                        // nt1
                        mma_bf16(acc[1], a0.x, a1.x, a2.x, a3.x, q0.z, q0.w);
                        mma_bf16(acc[1], a0.y, a1.y, a2.y, a3.y, q0.z, q0.w);
                        mma_bf16(acc[1], a0.x, a1.x, a2.x, a3.x, q2.z, q2.w);
                        // nt2
                        mma_bf16(acc[2], a0.x, a1.x, a2.x, a3.x, q1.x, q1.y);
                        mma_bf16(acc[2], a0.y, a1.y, a2.y, a3.y, q1.x, q1.y);
                        mma_bf16(acc[2], a0.x, a1.x, a2.x, a3.x, q3.x, q3.y);
                        // nt3
                        mma_bf16(acc[3], a0.x, a1.x, a2.x, a3.x, q1.z, q1.w);
                        mma_bf16(acc[3], a0.y, a1.y, a2.y, a3.y, q1.z, q1.w);
                        mma_bf16(acc[3], a0.x, a1.x, a2.x, a3.x, q3.z, q3.w);
                    }
                    // bias + ELU + split (phase-3 A fragments, registers)
                    #pragma unroll
                    for (int nt = 0; nt < 4; nt++) {
                        const float2 bias = *(const float2*)&b1[c * Gg + nt * 8 + 2 * tig];
                        float v0 = elu1(acc[nt][0] + bias.x);
                        float v1 = elu1(acc[nt][1] + bias.y);
                        float v2 = elu1(acc[nt][2] + bias.x);
                        float v3 = elu1(acc[nt][3] + bias.y);
                        split_pair(v0, v1, hfh[s][t][2 * nt],     hfl[s][t][2 * nt]);
                        split_pair(v2, v3, hfh[s][t][2 * nt + 1], hfl[s][t][2 * nt + 1]);
                    }
                }
                asm volatile("bar.arrive 2, 512;" ::: "memory");   // EMPTY
            }

            // ---------- Phase 3: Out = H @ W2^T + b2 (registers only) --------
            // Overlaps the producer's next mix (m buffer not touched here).
            #pragma unroll
            for (int s = 0; s < 2; s++) {
                const int c = 2 * cw + s;
                #pragma unroll
                for (int nt = 0; nt < 8; nt++) {
                    const int wb = ((c * 8 + nt) * 2) * 32 + lane;
                    const uint4 gh = W2pk[wb];
                    const uint4 gl = W2pk[wb + 32];
                    const float2 bias = *(const float2*)&b2[c * Dd + nt * 8 + 2 * tig];
                    #pragma unroll
                    for (int t = 0; t < 2; t++) {
                        const uint32_t* hh = hfh[s][t];
                        const uint32_t* hl = hfl[s][t];
                        float o[4] = {0.0f, 0.0f, 0.0f, 0.0f};
                        // kt'=0
                        mma_bf16(o, hh[0], hh[1], hh[2], hh[3], gh.x, gh.y);
                        mma_bf16(o, hl[0], hl[1], hl[2], hl[3], gh.x, gh.y);
                        mma_bf16(o, hh[0], hh[1], hh[2], hh[3], gl.x, gl.y);
                        // kt'=1
                        mma_bf16(o, hh[4], hh[5], hh[6], hh[7], gh.z, gh.w);
                        mma_bf16(o, hl[4], hl[5], hl[6], hl[7], gh.z, gh.w);
                        mma_bf16(o, hh[4], hh[5], hh[6], hh[7], gl.z, gl.w);

                        const int b0 = (2 * p + t) * 16;
                        float2 v0; v0.x = o[0] + bias.x; v0.y = o[1] + bias.y;
                        float2 v1; v1.x = o[2] + bias.x; v1.y = o[3] + bias.y;
                        __stcs((float2*)(out + ((size_t)(b0 + grp) * Cc + c) * Dd
                                             + nt * 8 + 2 * tig), v0);
                        __stcs((float2*)(out + ((size_t)(b0 + grp + 8) * Cc + c) * Dd
                                             + nt * 8 + 2 * tig), v1);
                    }
                }
            }
        }
    }
}

extern "C" void kernel_launch(void* const* d_in, const int* in_sizes, int n_in,
                              void* d_out, int out_size)
{
    const float* x  = (const float*)d_in[0];
    const float* A  = (const float*)d_in[1];
    const float* W1 = (const float*)d_in[2];
    const float* b1 = (const float*)d_in[3];
    const float* W2 = (const float*)d_in[4];
    const float* b2 = (const float*)d_in[5];
    float* out = (float*)d_out;

    const int Btot   = in_sizes[0] / (Cc * Dd);        // 65536
    const int nPairs = Btot / 32;                      // 2048

    int sms = 148;
    cudaDeviceGetAttribute(&sms, cudaDevAttrMultiProcessorCount, 0);

    pack_weights<<<64, 256>>>(W1, W2);
    cudaMemcpyToSymbolAsync(cA4, A, Cc * Cc * sizeof(float), 0,
                            cudaMemcpyDeviceToDevice);

    cudaFuncSetAttribute(causal_dag_kernel,
                         cudaFuncAttributeMaxDynamicSharedMemorySize, SMEM_TOTAL);
    causal_dag_kernel<<<sms, NTH, SMEM_TOTAL>>>(x, b1, b2, out, nPairs);
}